// round 9
// baseline (speedup 1.0000x reference)
#include <cuda_runtime.h>

#define CCH   512
#define HW    49
#define CHW   (CCH * HW)     // 25088 floats per sample
#define NTHR  1024
#define NW    (NTHR / 32)    // 32 warps
#define CPW   (CCH / NW)     // 16 channels per warp: 32 warps * 16 = 512 ✓
#define EPS   1e-5f

__global__ __launch_bounds__(NTHR, 1)
void gate_reg_kernel(const float* __restrict__ x, float* __restrict__ out, int N) {
    __shared__ float ys[CCH];     // per-channel spatial means
    __shared__ float gs[CCH];     // per-channel gates
    __shared__ float redA[NW];
    __shared__ float redB[NW];

    const int tid  = threadIdx.x;
    const int w    = tid >> 5;        // warp 0..31
    const int lane = tid & 31;
    const int c0   = w * CPW;         // first channel owned by this warp

    for (int s = blockIdx.x; s < N; s += gridDim.x) {
        const float* __restrict__ xs = x   + (size_t)s * CHW;
        float* __restrict__       os = out + (size_t)s * CHW;

        // ---- Load sample slice into registers + per-channel sums ----
        // Warp w owns channels [c0, c0+16). Per channel: lanes 0..31 read
        // floats 0..31, lanes 0..16 read floats 32..48 (49 total).
        float v0[CPW], v1[CPW];
        #pragma unroll
        for (int j = 0; j < CPW; j++) {
            const int base = (c0 + j) * HW;
            v0[j] = xs[base + lane];
            v1[j] = (lane < HW - 32) ? xs[base + 32 + lane] : 0.0f;
            float t = v0[j] + v1[j];
            #pragma unroll
            for (int off = 16; off > 0; off >>= 1)
                t += __shfl_xor_sync(0xffffffffu, t, off);
            if (lane == j) ys[c0 + j] = t * (1.0f / 49.0f);
        }
        __syncthreads();

        // ---- Block stats over 512 channels ----
        // Threads 0..511 each own one channel's y; others carry 0.
        const float y = (tid < CCH) ? ys[tid] : 0.0f;
        float a = y, b = y * y;
        #pragma unroll
        for (int off = 16; off > 0; off >>= 1) {
            a += __shfl_xor_sync(0xffffffffu, a, off);
            b += __shfl_xor_sync(0xffffffffu, b, off);
        }
        if (lane == 0) { redA[w] = a; redB[w] = b; }
        __syncthreads();

        // Every warp redundantly reduces the 32 partials -> stats in regs.
        a = redA[lane];
        b = redB[lane];
        #pragma unroll
        for (int off = 16; off > 0; off >>= 1) {
            a += __shfl_xor_sync(0xffffffffu, a, off);
            b += __shfl_xor_sync(0xffffffffu, b, off);
        }
        {
            const float m   = a * (1.0f / (float)CCH);
            const float mx2 = b * (1.0f / (float)CCH);
            float var = mx2 - m * m;
            var = var > 0.0f ? var : 0.0f;
            const float inv = rsqrtf(var + EPS);
            if (tid < CCH) {
                const float yn = (y - m) * inv;
                gs[tid] = __expf(-yn * yn);   // C_PARAM=2 -> exp(-yn^2)
            }
        }
        __syncthreads();

        // ---- Apply gate from registers, coalesced fire-and-forget STG ----
        #pragma unroll
        for (int j = 0; j < CPW; j++) {
            const int base = (c0 + j) * HW;
            const float g = gs[c0 + j];          // LDS broadcast
            os[base + lane] = v0[j] * g;
            if (lane < HW - 32)
                os[base + 32 + lane] = v1[j] * g;
        }
        // No trailing barrier needed:
        //  - ys[] of next iter is written pre-barrier-1, but all ys reads of
        //    this iter completed before barrier 2 (and every thread must pass
        //    barrier 1 of next iter only after ALL threads finished apply).
        //  - gs[] of next iter is written after next iter's barrier 2, which
        //    transitively requires every thread to have finished this apply.
    }
}

extern "C" void kernel_launch(void* const* d_in, const int* in_sizes, int n_in,
                              void* d_out, int out_size) {
    const float* x = (const float*)d_in[0];
    float* out = (float*)d_out;
    const int N = in_sizes[0] / CHW;   // 2048

    int sm_count = 0;
    if (cudaDeviceGetAttribute(&sm_count, cudaDevAttrMultiProcessorCount, 0)
        != cudaSuccess || sm_count <= 0)
        sm_count = 148;

    int grid = sm_count;               // 1 persistent CTA per SM
    if (grid > N) grid = N;

    gate_reg_kernel<<<grid, NTHR>>>(x, out, N);
}

// round 10
// speedup vs baseline: 1.3446x; 1.3446x over previous
#include <cuda_runtime.h>
#include <cstdint>

#define CCH   512
#define HW    49
#define CHW   (CCH * HW)          // 25088 floats per sample
#define NVEC  (CHW / 4)           // 6272 float4 per sample
#define NVEC2 (NVEC / 2)          // 3136 float4 per half
#define HALFF (CHW / 2)           // 12544 floats = 256 channels
#define NTHR  1024
#define EPS   1e-5f
#define TILE_BYTES (CHW * 4)      // 100352 B
#define HALF_BYTES (CHW * 2)      // 50176 B

// Stride of 1024 float4 = 4096 floats = 83*49 + 29
#define QSTEP 83
#define RSTEP 29

__device__ __forceinline__ uint32_t smem_u32(const void* p) {
    return (uint32_t)__cvta_generic_to_shared(p);
}
__device__ __forceinline__ void bulk_load(uint32_t dst, const void* src,
                                          uint32_t bytes, uint32_t mbar) {
    asm volatile(
        "cp.async.bulk.shared::cta.global.mbarrier::complete_tx::bytes [%0], [%1], %2, [%3];"
        :: "r"(dst), "l"(src), "r"(bytes), "r"(mbar) : "memory");
}
__device__ __forceinline__ void bulk_store(void* dst, uint32_t src, uint32_t bytes) {
    asm volatile(
        "cp.async.bulk.global.shared::cta.bulk_group [%0], [%1], %2;"
        :: "l"(dst), "r"(src), "r"(bytes) : "memory");
}
__device__ __forceinline__ void mbar_expect_tx(uint32_t mbar, uint32_t bytes) {
    asm volatile("mbarrier.arrive.expect_tx.shared.b64 _, [%0], %1;"
                 :: "r"(mbar), "r"(bytes) : "memory");
}
__device__ __forceinline__ void mbar_wait(uint32_t mbar, uint32_t parity) {
    asm volatile(
        "{\n\t"
        ".reg .pred P;\n\t"
        "WAIT_LP_%=:\n\t"
        "mbarrier.try_wait.parity.acquire.cta.shared::cta.b64 P, [%0], %1, 0x989680;\n\t"
        "@P bra.uni WAIT_DN_%=;\n\t"
        "bra.uni WAIT_LP_%=;\n\t"
        "WAIT_DN_%=:\n\t"
        "}"
        :: "r"(mbar), "r"(parity) : "memory");
}

__global__ __launch_bounds__(NTHR, 1)
void gate_pipe2_kernel(const float* __restrict__ x, float* __restrict__ out, int N) {
    extern __shared__ float smem[];           // 2 * CHW floats
    float* const tiles[2] = { smem, smem + CHW };
    __shared__ float part[NTHR];
    __shared__ float gateS[CCH + 8];
    __shared__ float redA[32];
    __shared__ float redB[32];
    __shared__ __align__(8) unsigned long long mbar_store[2];

    const int tid = threadIdx.x;
    const uint32_t mbA = smem_u32(&mbar_store[0]);
    const uint32_t mbB = smem_u32(&mbar_store[1]);

    if (tid == 0) {
        asm volatile("mbarrier.init.shared.b64 [%0], 1;" :: "r"(mbA) : "memory");
        asm volatile("mbarrier.init.shared.b64 [%0], 1;" :: "r"(mbB) : "memory");
    }
    __syncthreads();

    const int stride = gridDim.x;
    const int s0 = blockIdx.x;
    if (s0 >= N) return;

    // Prologue: both chunks of the first sample into buffer 0.
    if (tid == 0) {
        mbar_expect_tx(mbA, TILE_BYTES);
        const float* src = x + (size_t)s0 * CHW;
        bulk_load(smem_u32(tiles[0]),              src,         HALF_BYTES, mbA);
        bulk_load(smem_u32(tiles[0]) + HALF_BYTES, src + HALFF, HALF_BYTES, mbA);
    }

    uint32_t phA = 0, phB = 0;
    int idx = 0;
    for (int s = s0; s < N; s += stride, idx++) {
        const int b = idx & 1;
        float* tile = tiles[b];

        mbar_wait(b ? mbB : mbA, b ? phB : phA);
        if (b) phB ^= 1; else phA ^= 1;

        // ---- Reduce: per-channel sums, pair-split 25+24 ----
        {
            const int c    = tid & (CCH - 1);
            const int half = tid >> 9;
            const float* row = tile + c * HW + half * 25;
            const int cnt  = half ? 24 : 25;
            float sacc = 0.0f;
            #pragma unroll 5
            for (int j = 0; j < cnt; j++) sacc += row[j];
            part[tid] = sacc;
        }
        __syncthreads();

        float y = 0.0f;
        if (tid < CCH) y = (part[tid] + part[tid + CCH]) * (1.0f / 49.0f);

        float a = y, bb = y * y;
        #pragma unroll
        for (int off = 16; off > 0; off >>= 1) {
            a  += __shfl_xor_sync(0xffffffffu, a, off);
            bb += __shfl_xor_sync(0xffffffffu, bb, off);
        }
        const int wid = tid >> 5, lid = tid & 31;
        if (lid == 0) { redA[wid] = a; redB[wid] = bb; }
        __syncthreads();

        a  = redA[lid];
        bb = redB[lid];
        #pragma unroll
        for (int off = 16; off > 0; off >>= 1) {
            a  += __shfl_xor_sync(0xffffffffu, a, off);
            bb += __shfl_xor_sync(0xffffffffu, bb, off);
        }
        {
            const float m   = a  * (1.0f / (float)CCH);
            const float mx2 = bb * (1.0f / (float)CCH);
            float var = mx2 - m * m;
            var = var > 0.0f ? var : 0.0f;
            const float inv = rsqrtf(var + EPS);
            if (tid < CCH) {
                const float yn = (y - m) * inv;
                gateS[tid] = __expf(-yn * yn);    // C=2 -> exp(-yn^2)
            }
        }
        __syncthreads();

        const int sn = s + stride;
        const uint32_t dstn = smem_u32(tiles[b ^ 1]);
        const float*  srcn = x + (size_t)sn * CHW;

        // Refill chunk 1 of the other buffer. Outstanding store groups here:
        // {h1(idx-1), h2(idx-1)} on that buffer; wait_group 1 drains h1 only.
        if (sn < N && tid == 0) {
            asm volatile("cp.async.bulk.wait_group 1;" ::: "memory");
            mbar_expect_tx(b ? mbA : mbB, TILE_BYTES);
            bulk_load(dstn, srcn, HALF_BYTES, b ? mbA : mbB);
        }

        float4* tile4 = reinterpret_cast<float4*>(tile);

        // ---- Apply half 0 in place ----
        {
            int e = tid * 4;
            int q = e / HW;
            int r = e - q * HW;
            for (int i = tid; i < NVEC2; i += NTHR) {
                float4 v = tile4[i];
                const float g0 = gateS[q];
                const float g1 = gateS[q + 1];
                v.x *= g0;
                v.y *= (r + 1 >= HW) ? g1 : g0;
                v.z *= (r + 2 >= HW) ? g1 : g0;
                v.w *= (r + 3 >= HW) ? g1 : g0;
                tile4[i] = v;
                q += QSTEP; r += RSTEP;
                if (r >= HW) { r -= HW; q += 1; }
            }
        }
        __syncthreads();
        if (tid == 0) {
            asm volatile("fence.proxy.async.shared::cta;" ::: "memory");
            bulk_store(out + (size_t)s * CHW, smem_u32(tile), HALF_BYTES);
            asm volatile("cp.async.bulk.commit_group;" ::: "memory");
            if (sn < N) {
                // Outstanding: {h2(idx-1), h1(idx)}; drain h2(idx-1) only.
                asm volatile("cp.async.bulk.wait_group 1;" ::: "memory");
                bulk_load(dstn + HALF_BYTES, srcn + HALFF, HALF_BYTES,
                          b ? mbA : mbB);
            }
        }

        // ---- Apply half 1 in place ----
        {
            int e = (NVEC2 + tid) * 4;
            int q = e / HW;
            int r = e - q * HW;
            for (int i = tid; i < NVEC2; i += NTHR) {
                float4 v = tile4[NVEC2 + i];
                const float g0 = gateS[q];
                const float g1 = gateS[q + 1];
                v.x *= g0;
                v.y *= (r + 1 >= HW) ? g1 : g0;
                v.z *= (r + 2 >= HW) ? g1 : g0;
                v.w *= (r + 3 >= HW) ? g1 : g0;
                tile4[NVEC2 + i] = v;
                q += QSTEP; r += RSTEP;
                if (r >= HW) { r -= HW; q += 1; }
            }
        }
        __syncthreads();
        if (tid == 0) {
            asm volatile("fence.proxy.async.shared::cta;" ::: "memory");
            bulk_store(out + (size_t)s * CHW + HALFF,
                       smem_u32(tile) + HALF_BYTES, HALF_BYTES);
            asm volatile("cp.async.bulk.commit_group;" ::: "memory");
        }
    }

    if (tid == 0)
        asm volatile("cp.async.bulk.wait_group 0;" ::: "memory");
}

extern "C" void kernel_launch(void* const* d_in, const int* in_sizes, int n_in,
                              void* d_out, int out_size) {
    const float* x = (const float*)d_in[0];
    float* out = (float*)d_out;
    const int N = in_sizes[0] / CHW;   // 2048

    int sm_count = 0;
    if (cudaDeviceGetAttribute(&sm_count, cudaDevAttrMultiProcessorCount, 0)
        != cudaSuccess || sm_count <= 0)
        sm_count = 148;

    int grid = sm_count;
    if (grid > N) grid = N;

    const int dyn_smem = 2 * TILE_BYTES;   // 200,704 B
    cudaFuncSetAttribute(gate_pipe2_kernel,
                         cudaFuncAttributeMaxDynamicSharedMemorySize, dyn_smem);
    gate_pipe2_kernel<<<grid, NTHR, dyn_smem>>>(x, out, N);
}